// round 9
// baseline (speedup 1.0000x reference)
#include <cuda_runtime.h>
#include <cuda_bf16.h>
#include <cstdint>
#include <cstddef>

#define SEQ    2048
#define BATCH  128
#define INPUT  256
#define HIDDEN 512
#define MDIM   (SEQ * BATCH)          // 262144 GEMM rows

// ---------------------------------------------------------------------------
// Device scratch (no allocations allowed)
// ---------------------------------------------------------------------------
__device__ float g_xc[(size_t)SEQ * BATCH * HIDDEN];
__device__ float g_xa[(size_t)SEQ * BATCH * HIDDEN];
__device__ __nv_bfloat16 g_Ahi[(size_t)MDIM * INPUT];
__device__ __nv_bfloat16 g_Alo[(size_t)MDIM * INPUT];
__device__ __nv_bfloat16 g_Bhi[3 * HIDDEN * INPUT];
__device__ __nv_bfloat16 g_Blo[3 * HIDDEN * INPUT];
__device__ int g_flag[SEQ];           // per-timestep completion (12 = ready)

// ---------------------------------------------------------------------------
// PTX helpers (plain sm_80/sm_90-level PTX; assembles for compute_103)
// ---------------------------------------------------------------------------
__device__ __forceinline__ uint32_t smem_to_u32(const void* p) {
    uint32_t a;
    asm("{ .reg .u64 t; cvta.to.shared.u64 t, %1; cvt.u32.u64 %0, t; }"
        : "=r"(a) : "l"(p));
    return a;
}
__device__ __forceinline__ void cp16(uint32_t dst, const void* src) {
    asm volatile("cp.async.cg.shared.global [%0], [%1], 16;"
                 :: "r"(dst), "l"(src));
}
#define CP_COMMIT() asm volatile("cp.async.commit_group;" ::: "memory")
#define CP_WAIT(n)  asm volatile("cp.async.wait_group %0;" :: "n"(n) : "memory")

__device__ __forceinline__ void ldsm_x4(uint32_t* r, uint32_t addr) {
    asm volatile("ldmatrix.sync.aligned.m8n8.x4.shared.b16 {%0,%1,%2,%3}, [%4];"
                 : "=r"(r[0]), "=r"(r[1]), "=r"(r[2]), "=r"(r[3]) : "r"(addr));
}
__device__ __forceinline__ void mma16816(float* c, const uint32_t* a,
                                         const uint32_t* b) {
    asm volatile(
        "mma.sync.aligned.m16n8k16.row.col.f32.bf16.bf16.f32 "
        "{%0,%1,%2,%3}, {%4,%5,%6,%7}, {%8,%9}, {%0,%1,%2,%3};"
        : "+f"(c[0]), "+f"(c[1]), "+f"(c[2]), "+f"(c[3])
        : "r"(a[0]), "r"(a[1]), "r"(a[2]), "r"(a[3]), "r"(b[0]), "r"(b[1]));
}
__device__ __forceinline__ uint32_t sw128(uint32_t off) {
    return off ^ ((off >> 3) & 0x70);
}

// ---------------------------------------------------------------------------
// Pre-pass kernels
// ---------------------------------------------------------------------------
__global__ void resetFlags() {
    g_flag[blockIdx.x * blockDim.x + threadIdx.x] = 0;
}
__global__ void splitA(const float* __restrict__ x) {
    const size_t base = ((size_t)blockIdx.x * blockDim.x + threadIdx.x) * 8;
    float4 a = *(const float4*)(x + base);
    float4 b = *(const float4*)(x + base + 4);
    float f[8] = {a.x, a.y, a.z, a.w, b.x, b.y, b.z, b.w};
    union { __nv_bfloat16 h[8]; uint4 u; } H, L;
#pragma unroll
    for (int k = 0; k < 8; k++) {
        H.h[k] = __float2bfloat16_rn(f[k]);
        L.h[k] = __float2bfloat16_rn(f[k] - __bfloat162float(H.h[k]));
    }
    *(uint4*)(g_Ahi + base) = H.u;
    *(uint4*)(g_Alo + base) = L.u;
}
__global__ void splitB3(const float* __restrict__ Uc,
                        const float* __restrict__ Ua,
                        const float* __restrict__ Uh) {
    const int proj = blockIdx.y;
    const float* u = (proj == 0) ? Uc : (proj == 1) ? Ua : Uh;
    const size_t base = ((size_t)blockIdx.x * blockDim.x + threadIdx.x) * 8;
    const size_t off = (size_t)proj * HIDDEN * INPUT;
    float4 a = *(const float4*)(u + base);
    float4 b = *(const float4*)(u + base + 4);
    float f[8] = {a.x, a.y, a.z, a.w, b.x, b.y, b.z, b.w};
    union { __nv_bfloat16 h[8]; uint4 u4; } H, L;
#pragma unroll
    for (int k = 0; k < 8; k++) {
        H.h[k] = __float2bfloat16_rn(f[k]);
        L.h[k] = __float2bfloat16_rn(f[k] - __bfloat162float(H.h[k]));
    }
    *(uint4*)(g_Bhi + off + base) = H.u4;
    *(uint4*)(g_Blo + off + base) = L.u4;
}

// ---------------------------------------------------------------------------
// PERSISTENT mma.sync GEMM. grid = (12, 12) = 144 CTAs (one wave), block 256.
// CTA (colblk, i): B hi/lo for (proj, nb) resident (128 KB); sweeps
// yb = i, i+12, ... < 256; A K=64 chunks, 3 stages, copy lead 2, continuous
// pipeline across yb. Early griddepcontrol.launch_dependents lets the scan
// (PDL secondary) launch while this runs. Per-tile flag publish.
// ---------------------------------------------------------------------------
#define MATB     16384                 // 128 x 128 B
#define SM_B     0
#define SM_A     (8 * MATB)            // 3 stages x {hi, lo}
#define ASTAGE   (2 * MATB)
#define SM_BIAS  (SM_A + 3 * ASTAGE)   // 229376
#define SMEM_TOT (SM_BIAS + 512)       // 229888 bytes

__global__ __launch_bounds__(256, 1)
void brc_gemm_pb(const float* __restrict__ bc, const float* __restrict__ ba,
                 float* __restrict__ xh_out) {
    extern __shared__ __align__(1024) char smem[];
    const uint32_t sb = smem_to_u32(smem);
    const int tid = threadIdx.x;
    const int wid = tid >> 5;
    const int lid = tid & 31;

    const int colblk = blockIdx.x;     // 0..11
    const int proj   = colblk >> 2;
    const int nb     = colblk & 3;
    const int iy     = blockIdx.y;     // 0..11
    const int nyb    = (256 - iy + 11) / 12;
    const int NG     = nyb * 32;       // chunks this CTA processes

    float* __restrict__ C = (proj == 0) ? g_xc : (proj == 1) ? g_xa : xh_out;

    // bias -> smem (zero for proj 2)
    if (tid < 128) {
        float bv = 0.0f;
        if (proj == 0) bv = bc[nb * 128 + tid];
        else if (proj == 1) bv = ba[nb * 128 + tid];
        ((float*)(smem + SM_BIAS))[tid] = bv;
    }

    // ---- B preload: 8 mats (4 kc x hi/lo), 32 cp.async per thread ----
    {
        const __nv_bfloat16* Bh = g_Bhi + (size_t)proj * HIDDEN * INPUT
                                        + (size_t)(nb * 128) * INPUT;
        const __nv_bfloat16* Bl = g_Blo + (size_t)proj * HIDDEN * INPUT
                                        + (size_t)(nb * 128) * INPUT;
#pragma unroll
        for (int i = 0; i < 32; i++) {
            const int kcmat = i >> 2;
            const int kc = kcmat >> 1, hl = kcmat & 1;
            const int within = ((i & 3) << 8) + tid;
            const int r = within >> 3, s = within & 7;
            const __nv_bfloat16* g = ((hl == 0) ? Bh : Bl)
                                     + (size_t)r * INPUT + kc * 64 + s * 8;
            cp16(sb + (uint32_t)(SM_B + kcmat * MATB + sw128(r * 128 + s * 16)), g);
        }
        CP_COMMIT();
    }

    // All 144 blocks are resident in wave 1 -> trigger dependent (scan) launch
    asm volatile("griddepcontrol.launch_dependents;" ::: "memory");

    // A chunk g: yb = iy + (g>>5)*12, t = (g>>2)&7, kc = g&3; stage = g%3
    auto copy_A = [&](int g) {
        const int yb = iy + (g >> 5) * 12;
        const int t = (g >> 2) & 7, kc = g & 3;
        const size_t mrow = (size_t)(yb * 8 + t) * 128;
        const uint32_t stage = sb + (uint32_t)(SM_A + (g % 3) * ASTAGE);
#pragma unroll
        for (int i = 0; i < 8; i++) {
            const int hl = i >> 2;
            const int within = ((i & 3) << 8) + tid;
            const int r = within >> 3, s = within & 7;
            const __nv_bfloat16* gp = ((hl == 0) ? g_Ahi : g_Alo)
                + (mrow + r) * INPUT + kc * 64 + s * 8;
            cp16(stage + (uint32_t)(hl * MATB + sw128(r * 128 + s * 16)), gp);
        }
        CP_COMMIT();
    };
    copy_A(0);
    copy_A(1);

    // warp layout: 4(M) x 2(N); warp tile 32 x 64
    const int wm = wid & 3;
    const int wn = wid >> 2;
    const int aRow = wm * 32 + (lid & 15);
    const int aColE = (lid >> 4) << 3;
    const int bRow = wn * 64 + (lid & 7) + ((lid >> 4) << 3);
    const int bColE = ((lid >> 3) & 1) << 3;

    float cfr[2][8][4];
    const float* sBias = (const float*)(smem + SM_BIAS);

    for (int g = 0; g < NG; g++) {
        const int kc = g & 3;
        if (kc == 0) {
#pragma unroll
            for (int mt = 0; mt < 2; mt++)
#pragma unroll
                for (int nt = 0; nt < 8; nt++)
#pragma unroll
                    for (int p = 0; p < 4; p++) cfr[mt][nt][p] = 0.0f;
        }
        CP_WAIT(1);
        __syncthreads();            // also protects stage (g+2)%3 reuse
        if (g + 2 < NG) copy_A(g + 2);

        const uint32_t abuf = sb + (uint32_t)(SM_A + (g % 3) * ASTAGE);
        const uint32_t bbuf = sb + (uint32_t)(SM_B + kc * 2 * MATB);
#pragma unroll
        for (int k16 = 0; k16 < 4; k16++) {
            const int kcolb = k16 * 32;
            uint32_t ah[2][4], al[2][4], bb[8][2];
#pragma unroll
            for (int mt = 0; mt < 2; mt++)
                ldsm_x4(ah[mt], abuf + sw128((aRow + mt * 16) * 128
                                             + kcolb + aColE * 2));
#pragma unroll
            for (int pr = 0; pr < 4; pr++)          // B hi
                ldsm_x4(&bb[pr * 2][0], bbuf + sw128((bRow + pr * 16) * 128
                                                     + kcolb + bColE * 2));
#pragma unroll
            for (int mt = 0; mt < 2; mt++)
#pragma unroll
                for (int nt = 0; nt < 8; nt++)
                    mma16816(cfr[mt][nt], ah[mt], bb[nt]);
#pragma unroll
            for (int mt = 0; mt < 2; mt++)          // A lo
                ldsm_x4(al[mt], abuf + (uint32_t)MATB
                                + sw128((aRow + mt * 16) * 128
                                        + kcolb + aColE * 2));
#pragma unroll
            for (int mt = 0; mt < 2; mt++)
#pragma unroll
                for (int nt = 0; nt < 8; nt++)
                    mma16816(cfr[mt][nt], al[mt], bb[nt]);
#pragma unroll
            for (int pr = 0; pr < 4; pr++)          // B lo (reuse bb)
                ldsm_x4(&bb[pr * 2][0], bbuf + (uint32_t)MATB
                                        + sw128((bRow + pr * 16) * 128
                                                + kcolb + bColE * 2));
#pragma unroll
            for (int mt = 0; mt < 2; mt++)
#pragma unroll
                for (int nt = 0; nt < 8; nt++)
                    mma16816(cfr[mt][nt], ah[mt], bb[nt]);
        }

        if (kc == 3) {      // fp32 epilogue for this tile, then publish step
            const int yb = iy + (g >> 5) * 12;
            const int t = (g >> 2) & 7;
            const int step = yb * 8 + t;
            const int mbase = step * 128 + wm * 32 + (lid >> 2);
            const int t2 = (lid & 3) * 2;
#pragma unroll
            for (int mt = 0; mt < 2; mt++) {
                const size_t m0 = (size_t)(mbase + mt * 16);
#pragma unroll
                for (int nt = 0; nt < 8; nt++) {
                    const int ncol = wn * 64 + nt * 8 + t2;
                    const float b0 = sBias[ncol], b1 = sBias[ncol + 1];
                    float* p0 = C + m0 * HIDDEN + nb * 128 + ncol;
                    *(float2*)p0 = make_float2(cfr[mt][nt][0] + b0,
                                               cfr[mt][nt][1] + b1);
                    *(float2*)(p0 + 8 * HIDDEN) = make_float2(
                        cfr[mt][nt][2] + b0, cfr[mt][nt][3] + b1);
                }
            }
            __threadfence();                        // order stores (gpu scope)
            __syncthreads();                        // all threads' fences done
            if (tid == 0) atomicAdd(&g_flag[step], 1);
        }
    }
}

// ---------------------------------------------------------------------------
// Phase 2: flag-synchronized scan (PDL secondary on the same stream).
// MUFU sigmoid/tanh, prefetch depth 4, low-register build for co-residency.
// ---------------------------------------------------------------------------
#define PF 4
__device__ __forceinline__ void wait_flag(int s) {
    if ((threadIdx.x & 31) == 0) {
        while (*(volatile int*)&g_flag[s] < 12) __nanosleep(256);
    }
    __syncwarp();
    __threadfence();   // acquire: later reads see the producers' stores
}

__global__ __launch_bounds__(256, 6)
void brc_scan(float* __restrict__ out, const float* __restrict__ h0,
              const float* __restrict__ w_c, const float* __restrict__ w_a,
              float* __restrict__ hn) {
    const int tid = blockIdx.x * 256 + threadIdx.x;     // 0..65535
    const int j = tid & (HIDDEN - 1);
    const float wc = w_c[j];
    const float wa = w_a[j];
    float h = h0[tid];
    const int STRIDE = BATCH * HIDDEN;

    float xcb[PF], xab[PF], xhb[PF];
#pragma unroll
    for (int p = 0; p < PF; p++) {
        wait_flag(p);
        const size_t i = (size_t)p * STRIDE + tid;
        xcb[p] = __ldcs(g_xc + i);
        xab[p] = __ldcs(g_xa + i);
        xhb[p] = __ldcs(out + i);
    }

    size_t idx = (size_t)tid;
#pragma unroll 4
    for (int t = 0; t < SEQ; ++t, idx += STRIDE) {
        const int sl = t & (PF - 1);
        const float xc_c = xcb[sl], xa_c = xab[sl], xh_c = xhb[sl];
        if (t + PF < SEQ) {
            wait_flag(t + PF);
            const size_t nxt = idx + (size_t)PF * STRIDE;
            xcb[sl] = __ldcs(g_xc + nxt);
            xab[sl] = __ldcs(g_xa + nxt);
            xhb[sl] = __ldcs(out + nxt);
        }
        const float c  = __fdividef(1.0f, 1.0f + __expf(-(xc_c + wc * h)));
        const float ra = __fdividef(1.0f, 1.0f + __expf(2.0f * (xa_c + wa * h)));
        const float a  = fmaf(-2.0f, ra, 2.0f);          // 1 + tanh
        const float rh = __fdividef(1.0f, 1.0f + __expf(2.0f * (xh_c + a * h)));
        const float t3 = fmaf(-2.0f, rh, 1.0f);          // tanh
        h = fmaf(c, h - t3, t3);
        __stcs(out + idx, h);
    }
    if (hn) hn[tid] = h;
}

// ---------------------------------------------------------------------------
extern "C" void kernel_launch(void* const* d_in, const int* in_sizes, int n_in,
                              void* d_out, int out_size) {
    const float* x  = (const float*)d_in[0];
    const float* h0 = (const float*)d_in[1];
    const float* Uc = (const float*)d_in[2];
    const float* wc = (const float*)d_in[3];
    const float* bc = (const float*)d_in[4];
    const float* Ua = (const float*)d_in[5];
    const float* wa = (const float*)d_in[6];
    const float* ba = (const float*)d_in[7];
    const float* Uh = (const float*)d_in[8];

    float* out = (float*)d_out;
    const size_t out_elems = (size_t)SEQ * BATCH * HIDDEN;
    float* hn = ((size_t)out_size >= out_elems + (size_t)BATCH * HIDDEN)
                    ? (out + out_elems) : nullptr;

    // Pre-pass: reset flags + fp32 -> bf16 hi/lo splits
    resetFlags<<<SEQ / 256, 256>>>();
    splitA<<<(MDIM * INPUT / 8) / 256, 256>>>(x);
    dim3 gb(HIDDEN * INPUT / 8 / 256, 3);
    splitB3<<<gb, 256>>>(Uc, Ua, Uh);

    // Phase 1: persistent GEMM (144 CTAs, one wave)
    cudaFuncSetAttribute(brc_gemm_pb,
                         cudaFuncAttributeMaxDynamicSharedMemorySize, SMEM_TOT);
    dim3 grid(12, 12);
    brc_gemm_pb<<<grid, 256, SMEM_TOT>>>(bc, ba, out);

    // Phase 2: scan as PDL secondary on the SAME stream — launches once all
    // GEMM blocks have executed griddepcontrol.launch_dependents; flag-synced.
    cudaLaunchConfig_t cfg = {};
    cfg.gridDim  = dim3((BATCH * HIDDEN) / 256);
    cfg.blockDim = dim3(256);
    cfg.dynamicSmemBytes = 0;
    cfg.stream = 0;
    cudaLaunchAttribute attrs[1];
    attrs[0].id = cudaLaunchAttributeProgrammaticStreamSerialization;
    attrs[0].val.programmaticStreamSerializationAllowed = 1;
    cfg.attrs = attrs;
    cfg.numAttrs = 1;
    cudaError_t err = cudaLaunchKernelEx(&cfg, brc_scan, out, h0, wc, wa, hn);
    if (err != cudaSuccess) {
        // Fallback: plain launch (runs after GEMM completes; flags all 12)
        brc_scan<<<(BATCH * HIDDEN) / 256, 256>>>(out, h0, wc, wa, hn);
    }
}

// round 10
// speedup vs baseline: 2.6602x; 2.6602x over previous
#include <cuda_runtime.h>
#include <cuda_bf16.h>
#include <cstdint>
#include <cstddef>

#define SEQ    2048
#define BATCH  128
#define INPUT  256
#define HIDDEN 512
#define MDIM   (SEQ * BATCH)          // 262144 GEMM rows

// ---------------------------------------------------------------------------
// Device scratch (no allocations allowed)
// ---------------------------------------------------------------------------
__device__ float g_xc[(size_t)SEQ * BATCH * HIDDEN];
__device__ float g_xa[(size_t)SEQ * BATCH * HIDDEN];
__device__ __nv_bfloat16 g_Ahi[(size_t)MDIM * INPUT];
__device__ __nv_bfloat16 g_Alo[(size_t)MDIM * INPUT];
__device__ __nv_bfloat16 g_Bhi[3 * HIDDEN * INPUT];
__device__ __nv_bfloat16 g_Blo[3 * HIDDEN * INPUT];

// ---------------------------------------------------------------------------
// PTX helpers (plain sm_80-level PTX; assembles for compute_103)
// ---------------------------------------------------------------------------
__device__ __forceinline__ uint32_t smem_to_u32(const void* p) {
    uint32_t a;
    asm("{ .reg .u64 t; cvta.to.shared.u64 t, %1; cvt.u32.u64 %0, t; }"
        : "=r"(a) : "l"(p));
    return a;
}
__device__ __forceinline__ void cp16(uint32_t dst, const void* src) {
    asm volatile("cp.async.cg.shared.global [%0], [%1], 16;"
                 :: "r"(dst), "l"(src));
}
#define CP_COMMIT() asm volatile("cp.async.commit_group;" ::: "memory")
#define CP_WAIT(n)  asm volatile("cp.async.wait_group %0;" :: "n"(n) : "memory")

__device__ __forceinline__ void ldsm_x4(uint32_t* r, uint32_t addr) {
    asm volatile("ldmatrix.sync.aligned.m8n8.x4.shared.b16 {%0,%1,%2,%3}, [%4];"
                 : "=r"(r[0]), "=r"(r[1]), "=r"(r[2]), "=r"(r[3]) : "r"(addr));
}
__device__ __forceinline__ void mma16816(float* c, const uint32_t* a,
                                         const uint32_t* b) {
    asm volatile(
        "mma.sync.aligned.m16n8k16.row.col.f32.bf16.bf16.f32 "
        "{%0,%1,%2,%3}, {%4,%5,%6,%7}, {%8,%9}, {%0,%1,%2,%3};"
        : "+f"(c[0]), "+f"(c[1]), "+f"(c[2]), "+f"(c[3])
        : "r"(a[0]), "r"(a[1]), "r"(a[2]), "r"(a[3]), "r"(b[0]), "r"(b[1]));
}
__device__ __forceinline__ uint32_t sw128(uint32_t off) {
    return off ^ ((off >> 3) & 0x70);
}

// ---------------------------------------------------------------------------
// Pre-pass: split fp32 -> bf16 hi/lo
// ---------------------------------------------------------------------------
__global__ void splitA(const float* __restrict__ x) {
    const size_t base = ((size_t)blockIdx.x * blockDim.x + threadIdx.x) * 8;
    float4 a = *(const float4*)(x + base);
    float4 b = *(const float4*)(x + base + 4);
    float f[8] = {a.x, a.y, a.z, a.w, b.x, b.y, b.z, b.w};
    union { __nv_bfloat16 h[8]; uint4 u; } H, L;
#pragma unroll
    for (int k = 0; k < 8; k++) {
        H.h[k] = __float2bfloat16_rn(f[k]);
        L.h[k] = __float2bfloat16_rn(f[k] - __bfloat162float(H.h[k]));
    }
    *(uint4*)(g_Ahi + base) = H.u;
    *(uint4*)(g_Alo + base) = L.u;
}
__global__ void splitB3(const float* __restrict__ Uc,
                        const float* __restrict__ Ua,
                        const float* __restrict__ Uh) {
    const int proj = blockIdx.y;
    const float* u = (proj == 0) ? Uc : (proj == 1) ? Ua : Uh;
    const size_t base = ((size_t)blockIdx.x * blockDim.x + threadIdx.x) * 8;
    const size_t off = (size_t)proj * HIDDEN * INPUT;
    float4 a = *(const float4*)(u + base);
    float4 b = *(const float4*)(u + base + 4);
    float f[8] = {a.x, a.y, a.z, a.w, b.x, b.y, b.z, b.w};
    union { __nv_bfloat16 h[8]; uint4 u4; } H, L;
#pragma unroll
    for (int k = 0; k < 8; k++) {
        H.h[k] = __float2bfloat16_rn(f[k]);
        L.h[k] = __float2bfloat16_rn(f[k] - __bfloat162float(H.h[k]));
    }
    *(uint4*)(g_Bhi + off + base) = H.u4;
    *(uint4*)(g_Blo + off + base) = L.u4;
}

// ---------------------------------------------------------------------------
// Persistent-B mma.sync GEMM (R7 shape, unchanged). grid = (12, 256),
// block = 256. B hi/lo resident (128 KB); 8 M-tiles per CTA; A streamed in
// K=64 chunks, THREE 32 KB stages, copy lead 2, one __syncthreads per chunk.
// 3 split terms: Ah*Bh + Al*Bh + Ah*Bl. fp32 accumulate + bias epilogue.
// ---------------------------------------------------------------------------
#define MATB     16384                 // 128 x 128 B
#define SM_B     0                     // 8 mats: (kc*2+hl)*MATB, kc 0..3
#define SM_A     (8 * MATB)            // 3 stages x {hi, lo}
#define ASTAGE   (2 * MATB)
#define SM_BIAS  (SM_A + 3 * ASTAGE)   // 229376
#define SMEM_TOT (SM_BIAS + 512)       // 229888 bytes
#define TILES    8
#define NQ       (TILES * 4)           // 32 K-chunks

__global__ __launch_bounds__(256, 1)
void brc_gemm_pb(const float* __restrict__ bc, const float* __restrict__ ba,
                 float* __restrict__ xh_out) {
    extern __shared__ __align__(1024) char smem[];
    const uint32_t sb = smem_to_u32(smem);
    const int tid = threadIdx.x;
    const int wid = tid >> 5;
    const int lid = tid & 31;

    const int colblk = blockIdx.x;     // 0..11
    const int proj   = colblk >> 2;
    const int nb     = colblk & 3;
    const int yb     = blockIdx.y;     // 0..255

    float* __restrict__ C = (proj == 0) ? g_xc : (proj == 1) ? g_xa : xh_out;

    // bias -> smem (zero for proj 2)
    if (tid < 128) {
        float bv = 0.0f;
        if (proj == 0) bv = bc[nb * 128 + tid];
        else if (proj == 1) bv = ba[nb * 128 + tid];
        ((float*)(smem + SM_BIAS))[tid] = bv;
    }

    // ---- B preload: 8 mats (4 kc x hi/lo), 32 cp.async per thread ----
    {
        const __nv_bfloat16* Bh = g_Bhi + (size_t)proj * HIDDEN * INPUT
                                        + (size_t)(nb * 128) * INPUT;
        const __nv_bfloat16* Bl = g_Blo + (size_t)proj * HIDDEN * INPUT
                                        + (size_t)(nb * 128) * INPUT;
#pragma unroll
        for (int i = 0; i < 32; i++) {
            const int kcmat = i >> 2;              // 0..7
            const int kc = kcmat >> 1, hl = kcmat & 1;
            const int within = ((i & 3) << 8) + tid;   // 0..1023
            const int r = within >> 3, s = within & 7;
            const __nv_bfloat16* g = ((hl == 0) ? Bh : Bl)
                                     + (size_t)r * INPUT + kc * 64 + s * 8;
            cp16(sb + (uint32_t)(SM_B + kcmat * MATB + sw128(r * 128 + s * 16)), g);
        }
        CP_COMMIT();
    }

    // A chunk copy: q (0..31): tile t = q>>2, kc = q&3; stage = q%3
    auto copy_A = [&](int q) {
        const int t = q >> 2, kc = q & 3;
        const size_t mrow = (size_t)(yb * 8 + t) * 128;
        const uint32_t stage = sb + (uint32_t)(SM_A + (q % 3) * ASTAGE);
#pragma unroll
        for (int i = 0; i < 8; i++) {
            const int hl = i >> 2;
            const int within = ((i & 3) << 8) + tid;
            const int r = within >> 3, s = within & 7;
            const __nv_bfloat16* g = ((hl == 0) ? g_Ahi : g_Alo)
                + (mrow + r) * INPUT + kc * 64 + s * 8;
            cp16(stage + (uint32_t)(hl * MATB + sw128(r * 128 + s * 16)), g);
        }
        CP_COMMIT();
    };
    copy_A(0);
    copy_A(1);

    // warp layout: 4(M) x 2(N); warp tile 32 x 64
    const int wm = wid & 3;
    const int wn = wid >> 2;
    const int aRow = wm * 32 + (lid & 15);          // + mt*16
    const int aColE = (lid >> 4) << 3;              // 0/8, + k16*16
    const int bRow = wn * 64 + (lid & 7) + ((lid >> 4) << 3);  // + pr*16
    const int bColE = ((lid >> 3) & 1) << 3;        // 0/8, + k16*16

    float cfr[2][8][4];
    const float* sBias = (const float*)(smem + SM_BIAS);

    for (int q = 0; q < NQ; q++) {
        const int kc = q & 3;
        if (kc == 0) {
#pragma unroll
            for (int mt = 0; mt < 2; mt++)
#pragma unroll
                for (int nt = 0; nt < 8; nt++)
#pragma unroll
                    for (int p = 0; p < 4; p++) cfr[mt][nt][p] = 0.0f;
        }
        CP_WAIT(1);
        __syncthreads();            // also protects stage (q+2)%3 reuse
        if (q + 2 < NQ) copy_A(q + 2);

        const uint32_t abuf = sb + (uint32_t)(SM_A + (q % 3) * ASTAGE);
        const uint32_t bbuf = sb + (uint32_t)(SM_B + kc * 2 * MATB);
#pragma unroll
        for (int k16 = 0; k16 < 4; k16++) {
            const int kcolb = k16 * 32;             // byte col of k16 block
            uint32_t ah[2][4], al[2][4], bb[8][2];
#pragma unroll
            for (int mt = 0; mt < 2; mt++)
                ldsm_x4(ah[mt], abuf + sw128((aRow + mt * 16) * 128
                                             + kcolb + aColE * 2));
#pragma unroll
            for (int pr = 0; pr < 4; pr++)          // B hi
                ldsm_x4(&bb[pr * 2][0], bbuf + sw128((bRow + pr * 16) * 128
                                                     + kcolb + bColE * 2));
#pragma unroll
            for (int mt = 0; mt < 2; mt++)
#pragma unroll
                for (int nt = 0; nt < 8; nt++)
                    mma16816(cfr[mt][nt], ah[mt], bb[nt]);
#pragma unroll
            for (int mt = 0; mt < 2; mt++)          // A lo
                ldsm_x4(al[mt], abuf + (uint32_t)MATB
                                + sw128((aRow + mt * 16) * 128
                                        + kcolb + aColE * 2));
#pragma unroll
            for (int mt = 0; mt < 2; mt++)
#pragma unroll
                for (int nt = 0; nt < 8; nt++)
                    mma16816(cfr[mt][nt], al[mt], bb[nt]);
#pragma unroll
            for (int pr = 0; pr < 4; pr++)          // B lo (reuse bb)
                ldsm_x4(&bb[pr * 2][0], bbuf + (uint32_t)MATB
                                        + sw128((bRow + pr * 16) * 128
                                                + kcolb + bColE * 2));
#pragma unroll
            for (int mt = 0; mt < 2; mt++)
#pragma unroll
                for (int nt = 0; nt < 8; nt++)
                    mma16816(cfr[mt][nt], ah[mt], bb[nt]);
        }

        if (kc == 3) {      // fp32 epilogue for tile t
            const int t = q >> 2;
            const int mbase = (yb * 8 + t) * 128 + wm * 32 + (lid >> 2);
            const int t2 = (lid & 3) * 2;
#pragma unroll
            for (int mt = 0; mt < 2; mt++) {
                const size_t m0 = (size_t)(mbase + mt * 16);
#pragma unroll
                for (int nt = 0; nt < 8; nt++) {
                    const int ncol = wn * 64 + nt * 8 + t2;
                    const float b0 = sBias[ncol], b1 = sBias[ncol + 1];
                    float* p0 = C + m0 * HIDDEN + nb * 128 + ncol;
                    *(float2*)p0 = make_float2(cfr[mt][nt][0] + b0,
                                               cfr[mt][nt][1] + b1);
                    *(float2*)(p0 + 8 * HIDDEN) = make_float2(
                        cfr[mt][nt][2] + b0, cfr[mt][nt][3] + b1);
                }
            }
        }
    }
}

// ---------------------------------------------------------------------------
// Phase 2: scan, float2-vectorized (2 independent h-chains per thread, ILP 2),
// MUFU sigmoid/tanh, prefetch depth 8, streaming loads/stores.
// 32768 threads, each owns elements (2*gt, 2*gt+1).
// ---------------------------------------------------------------------------
#define PF 8
__global__ __launch_bounds__(128)
void brc_scan(float* __restrict__ out, const float* __restrict__ h0,
              const float* __restrict__ w_c, const float* __restrict__ w_a,
              float* __restrict__ hn) {
    const int gt = blockIdx.x * 128 + threadIdx.x;      // 0..32767
    const int e0 = gt * 2;                              // element index
    const int j = e0 & (HIDDEN - 1);
    const float2 wc = *(const float2*)(w_c + j);
    const float2 wa = *(const float2*)(w_a + j);
    float2 h = *(const float2*)(h0 + e0);
    const int STRIDE = BATCH * HIDDEN;                  // 65536 floats

    const float2* XC = (const float2*)g_xc;
    const float2* XA = (const float2*)g_xa;
    float2* OUT = (float2*)out;
    const int S2 = STRIDE / 2;                          // float2 stride

    float2 xcb[PF], xab[PF], xhb[PF];
#pragma unroll
    for (int p = 0; p < PF; p++) {
        const size_t i = (size_t)p * S2 + gt;
        xcb[p] = __ldcs(XC + i);
        xab[p] = __ldcs(XA + i);
        xhb[p] = __ldcs(OUT + i);
    }

    size_t idx = (size_t)gt;
#pragma unroll 8
    for (int t = 0; t < SEQ; ++t, idx += S2) {
        const int sl = t & (PF - 1);
        const float2 xc_c = xcb[sl], xa_c = xab[sl], xh_c = xhb[sl];
        if (t + PF < SEQ) {
            const size_t nxt = idx + (size_t)PF * S2;
            xcb[sl] = __ldcs(XC + nxt);
            xab[sl] = __ldcs(XA + nxt);
            xhb[sl] = __ldcs(OUT + nxt);
        }
        // lane x
        {
            const float c  = __fdividef(1.0f, 1.0f + __expf(-(xc_c.x + wc.x * h.x)));
            const float ra = __fdividef(1.0f, 1.0f + __expf(2.0f * (xa_c.x + wa.x * h.x)));
            const float a  = fmaf(-2.0f, ra, 2.0f);
            const float rh = __fdividef(1.0f, 1.0f + __expf(2.0f * (xh_c.x + a * h.x)));
            const float t3 = fmaf(-2.0f, rh, 1.0f);
            h.x = fmaf(c, h.x - t3, t3);
        }
        // lane y
        {
            const float c  = __fdividef(1.0f, 1.0f + __expf(-(xc_c.y + wc.y * h.y)));
            const float ra = __fdividef(1.0f, 1.0f + __expf(2.0f * (xa_c.y + wa.y * h.y)));
            const float a  = fmaf(-2.0f, ra, 2.0f);
            const float rh = __fdividef(1.0f, 1.0f + __expf(2.0f * (xh_c.y + a * h.y)));
            const float t3 = fmaf(-2.0f, rh, 1.0f);
            h.y = fmaf(c, h.y - t3, t3);
        }
        __stcs(OUT + idx, h);
    }
    if (hn) *(float2*)(hn + e0) = h;
}

// ---------------------------------------------------------------------------
extern "C" void kernel_launch(void* const* d_in, const int* in_sizes, int n_in,
                              void* d_out, int out_size) {
    const float* x  = (const float*)d_in[0];
    const float* h0 = (const float*)d_in[1];
    const float* Uc = (const float*)d_in[2];
    const float* wc = (const float*)d_in[3];
    const float* bc = (const float*)d_in[4];
    const float* Ua = (const float*)d_in[5];
    const float* wa = (const float*)d_in[6];
    const float* ba = (const float*)d_in[7];
    const float* Uh = (const float*)d_in[8];

    float* out = (float*)d_out;
    const size_t out_elems = (size_t)SEQ * BATCH * HIDDEN;
    float* hn = ((size_t)out_size >= out_elems + (size_t)BATCH * HIDDEN)
                    ? (out + out_elems) : nullptr;

    // Pre-pass: fp32 -> bf16 hi/lo splits
    splitA<<<(MDIM * INPUT / 8) / 256, 256>>>(x);
    dim3 gb(HIDDEN * INPUT / 8 / 256, 3);
    splitB3<<<gb, 256>>>(Uc, Ua, Uh);

    // Phase 1: persistent-B mma.sync GEMMs (3-stage A pipeline)
    cudaFuncSetAttribute(brc_gemm_pb,
                         cudaFuncAttributeMaxDynamicSharedMemorySize, SMEM_TOT);
    dim3 grid(12, 256);
    brc_gemm_pb<<<grid, 256, SMEM_TOT>>>(bc, ba, out);

    // Phase 2: recurrent scan, float2 lanes, in place over xh
    brc_scan<<<(BATCH * HIDDEN / 2) / 128, 128>>>(out, h0, wc, wa, hn);
}

// round 11
// speedup vs baseline: 2.7255x; 1.0245x over previous
#include <cuda_runtime.h>
#include <cuda_bf16.h>
#include <cstdint>
#include <cstddef>

#define SEQ    2048
#define BATCH  128
#define INPUT  256
#define HIDDEN 512
#define MDIM   (SEQ * BATCH)          // 262144 GEMM rows

// ---------------------------------------------------------------------------
// Device scratch (no allocations allowed)
// ---------------------------------------------------------------------------
__device__ float g_xc[(size_t)SEQ * BATCH * HIDDEN];
__device__ float g_xa[(size_t)SEQ * BATCH * HIDDEN];
__device__ __nv_bfloat16 g_Ahi[(size_t)MDIM * INPUT];
__device__ __nv_bfloat16 g_Alo[(size_t)MDIM * INPUT];
__device__ __nv_bfloat16 g_Bhi[3 * HIDDEN * INPUT];
__device__ __nv_bfloat16 g_Blo[3 * HIDDEN * INPUT];

// ---------------------------------------------------------------------------
// PTX helpers (plain sm_75/80-level PTX; assembles for compute_103)
// ---------------------------------------------------------------------------
__device__ __forceinline__ uint32_t smem_to_u32(const void* p) {
    uint32_t a;
    asm("{ .reg .u64 t; cvta.to.shared.u64 t, %1; cvt.u32.u64 %0, t; }"
        : "=r"(a) : "l"(p));
    return a;
}
__device__ __forceinline__ void cp16(uint32_t dst, const void* src) {
    asm volatile("cp.async.cg.shared.global [%0], [%1], 16;"
                 :: "r"(dst), "l"(src));
}
#define CP_COMMIT() asm volatile("cp.async.commit_group;" ::: "memory")
#define CP_WAIT(n)  asm volatile("cp.async.wait_group %0;" :: "n"(n) : "memory")

__device__ __forceinline__ void ldsm_x4(uint32_t* r, uint32_t addr) {
    asm volatile("ldmatrix.sync.aligned.m8n8.x4.shared.b16 {%0,%1,%2,%3}, [%4];"
                 : "=r"(r[0]), "=r"(r[1]), "=r"(r[2]), "=r"(r[3]) : "r"(addr));
}
__device__ __forceinline__ void mma16816(float* c, const uint32_t* a,
                                         const uint32_t* b) {
    asm volatile(
        "mma.sync.aligned.m16n8k16.row.col.f32.bf16.bf16.f32 "
        "{%0,%1,%2,%3}, {%4,%5,%6,%7}, {%8,%9}, {%0,%1,%2,%3};"
        : "+f"(c[0]), "+f"(c[1]), "+f"(c[2]), "+f"(c[3])
        : "r"(a[0]), "r"(a[1]), "r"(a[2]), "r"(a[3]), "r"(b[0]), "r"(b[1]));
}
__device__ __forceinline__ uint32_t sw128(uint32_t off) {
    return off ^ ((off >> 3) & 0x70);
}
__device__ __forceinline__ float tanh_ap(float x) {
    float y;
    asm("tanh.approx.f32 %0, %1;" : "=f"(y) : "f"(x));
    return y;
}

// ---------------------------------------------------------------------------
// Pre-pass: split fp32 -> bf16 hi/lo
// ---------------------------------------------------------------------------
__global__ void splitA(const float* __restrict__ x) {
    const size_t base = ((size_t)blockIdx.x * blockDim.x + threadIdx.x) * 8;
    float4 a = *(const float4*)(x + base);
    float4 b = *(const float4*)(x + base + 4);
    float f[8] = {a.x, a.y, a.z, a.w, b.x, b.y, b.z, b.w};
    union { __nv_bfloat16 h[8]; uint4 u; } H, L;
#pragma unroll
    for (int k = 0; k < 8; k++) {
        H.h[k] = __float2bfloat16_rn(f[k]);
        L.h[k] = __float2bfloat16_rn(f[k] - __bfloat162float(H.h[k]));
    }
    *(uint4*)(g_Ahi + base) = H.u;
    *(uint4*)(g_Alo + base) = L.u;
}
__global__ void splitB3(const float* __restrict__ Uc,
                        const float* __restrict__ Ua,
                        const float* __restrict__ Uh) {
    const int proj = blockIdx.y;
    const float* u = (proj == 0) ? Uc : (proj == 1) ? Ua : Uh;
    const size_t base = ((size_t)blockIdx.x * blockDim.x + threadIdx.x) * 8;
    const size_t off = (size_t)proj * HIDDEN * INPUT;
    float4 a = *(const float4*)(u + base);
    float4 b = *(const float4*)(u + base + 4);
    float f[8] = {a.x, a.y, a.z, a.w, b.x, b.y, b.z, b.w};
    union { __nv_bfloat16 h[8]; uint4 u4; } H, L;
#pragma unroll
    for (int k = 0; k < 8; k++) {
        H.h[k] = __float2bfloat16_rn(f[k]);
        L.h[k] = __float2bfloat16_rn(f[k] - __bfloat162float(H.h[k]));
    }
    *(uint4*)(g_Bhi + off + base) = H.u4;
    *(uint4*)(g_Blo + off + base) = L.u4;
}

// ---------------------------------------------------------------------------
// Persistent-B mma.sync GEMM (unchanged from best). grid = (12, 256),
// block = 256. B hi/lo resident (128 KB); 8 M-tiles per CTA; A streamed in
// K=64 chunks, THREE 32 KB stages, copy lead 2, one __syncthreads per chunk.
// 3 split terms: Ah*Bh + Al*Bh + Ah*Bl. fp32 accumulate + bias epilogue.
// ---------------------------------------------------------------------------
#define MATB     16384                 // 128 x 128 B
#define SM_B     0                     // 8 mats: (kc*2+hl)*MATB, kc 0..3
#define SM_A     (8 * MATB)            // 3 stages x {hi, lo}
#define ASTAGE   (2 * MATB)
#define SM_BIAS  (SM_A + 3 * ASTAGE)   // 229376
#define SMEM_TOT (SM_BIAS + 512)       // 229888 bytes
#define TILES    8
#define NQ       (TILES * 4)           // 32 K-chunks

__global__ __launch_bounds__(256, 1)
void brc_gemm_pb(const float* __restrict__ bc, const float* __restrict__ ba,
                 float* __restrict__ xh_out) {
    extern __shared__ __align__(1024) char smem[];
    const uint32_t sb = smem_to_u32(smem);
    const int tid = threadIdx.x;
    const int wid = tid >> 5;
    const int lid = tid & 31;

    const int colblk = blockIdx.x;     // 0..11
    const int proj   = colblk >> 2;
    const int nb     = colblk & 3;
    const int yb     = blockIdx.y;     // 0..255

    float* __restrict__ C = (proj == 0) ? g_xc : (proj == 1) ? g_xa : xh_out;

    // bias -> smem (zero for proj 2)
    if (tid < 128) {
        float bv = 0.0f;
        if (proj == 0) bv = bc[nb * 128 + tid];
        else if (proj == 1) bv = ba[nb * 128 + tid];
        ((float*)(smem + SM_BIAS))[tid] = bv;
    }

    // ---- B preload: 8 mats (4 kc x hi/lo), 32 cp.async per thread ----
    {
        const __nv_bfloat16* Bh = g_Bhi + (size_t)proj * HIDDEN * INPUT
                                        + (size_t)(nb * 128) * INPUT;
        const __nv_bfloat16* Bl = g_Blo + (size_t)proj * HIDDEN * INPUT
                                        + (size_t)(nb * 128) * INPUT;
#pragma unroll
        for (int i = 0; i < 32; i++) {
            const int kcmat = i >> 2;              // 0..7
            const int kc = kcmat >> 1, hl = kcmat & 1;
            const int within = ((i & 3) << 8) + tid;   // 0..1023
            const int r = within >> 3, s = within & 7;
            const __nv_bfloat16* g = ((hl == 0) ? Bh : Bl)
                                     + (size_t)r * INPUT + kc * 64 + s * 8;
            cp16(sb + (uint32_t)(SM_B + kcmat * MATB + sw128(r * 128 + s * 16)), g);
        }
        CP_COMMIT();
    }

    // A chunk copy: q (0..31): tile t = q>>2, kc = q&3; stage = q%3
    auto copy_A = [&](int q) {
        const int t = q >> 2, kc = q & 3;
        const size_t mrow = (size_t)(yb * 8 + t) * 128;
        const uint32_t stage = sb + (uint32_t)(SM_A + (q % 3) * ASTAGE);
#pragma unroll
        for (int i = 0; i < 8; i++) {
            const int hl = i >> 2;
            const int within = ((i & 3) << 8) + tid;
            const int r = within >> 3, s = within & 7;
            const __nv_bfloat16* g = ((hl == 0) ? g_Ahi : g_Alo)
                + (mrow + r) * INPUT + kc * 64 + s * 8;
            cp16(stage + (uint32_t)(hl * MATB + sw128(r * 128 + s * 16)), g);
        }
        CP_COMMIT();
    };
    copy_A(0);
    copy_A(1);

    // warp layout: 4(M) x 2(N); warp tile 32 x 64
    const int wm = wid & 3;
    const int wn = wid >> 2;
    const int aRow = wm * 32 + (lid & 15);          // + mt*16
    const int aColE = (lid >> 4) << 3;              // 0/8, + k16*16
    const int bRow = wn * 64 + (lid & 7) + ((lid >> 4) << 3);  // + pr*16
    const int bColE = ((lid >> 3) & 1) << 3;        // 0/8, + k16*16

    float cfr[2][8][4];
    const float* sBias = (const float*)(smem + SM_BIAS);

    for (int q = 0; q < NQ; q++) {
        const int kc = q & 3;
        if (kc == 0) {
#pragma unroll
            for (int mt = 0; mt < 2; mt++)
#pragma unroll
                for (int nt = 0; nt < 8; nt++)
#pragma unroll
                    for (int p = 0; p < 4; p++) cfr[mt][nt][p] = 0.0f;
        }
        CP_WAIT(1);
        __syncthreads();            // also protects stage (q+2)%3 reuse
        if (q + 2 < NQ) copy_A(q + 2);

        const uint32_t abuf = sb + (uint32_t)(SM_A + (q % 3) * ASTAGE);
        const uint32_t bbuf = sb + (uint32_t)(SM_B + kc * 2 * MATB);
#pragma unroll
        for (int k16 = 0; k16 < 4; k16++) {
            const int kcolb = k16 * 32;             // byte col of k16 block
            uint32_t ah[2][4], al[2][4], bb[8][2];
#pragma unroll
            for (int mt = 0; mt < 2; mt++)
                ldsm_x4(ah[mt], abuf + sw128((aRow + mt * 16) * 128
                                             + kcolb + aColE * 2));
#pragma unroll
            for (int pr = 0; pr < 4; pr++)          // B hi
                ldsm_x4(&bb[pr * 2][0], bbuf + sw128((bRow + pr * 16) * 128
                                                     + kcolb + bColE * 2));
#pragma unroll
            for (int mt = 0; mt < 2; mt++)
#pragma unroll
                for (int nt = 0; nt < 8; nt++)
                    mma16816(cfr[mt][nt], ah[mt], bb[nt]);
#pragma unroll
            for (int mt = 0; mt < 2; mt++)          // A lo
                ldsm_x4(al[mt], abuf + (uint32_t)MATB
                                + sw128((aRow + mt * 16) * 128
                                        + kcolb + aColE * 2));
#pragma unroll
            for (int mt = 0; mt < 2; mt++)
#pragma unroll
                for (int nt = 0; nt < 8; nt++)
                    mma16816(cfr[mt][nt], al[mt], bb[nt]);
#pragma unroll
            for (int pr = 0; pr < 4; pr++)          // B lo (reuse bb)
                ldsm_x4(&bb[pr * 2][0], bbuf + (uint32_t)MATB
                                        + sw128((bRow + pr * 16) * 128
                                                + kcolb + bColE * 2));
#pragma unroll
            for (int mt = 0; mt < 2; mt++)
#pragma unroll
                for (int nt = 0; nt < 8; nt++)
                    mma16816(cfr[mt][nt], ah[mt], bb[nt]);
        }

        if (kc == 3) {      // fp32 epilogue for tile t
            const int t = q >> 2;
            const int mbase = (yb * 8 + t) * 128 + wm * 32 + (lid >> 2);
            const int t2 = (lid & 3) * 2;
#pragma unroll
            for (int mt = 0; mt < 2; mt++) {
                const size_t m0 = (size_t)(mbase + mt * 16);
#pragma unroll
                for (int nt = 0; nt < 8; nt++) {
                    const int ncol = wn * 64 + nt * 8 + t2;
                    const float b0 = sBias[ncol], b1 = sBias[ncol + 1];
                    float* p0 = C + m0 * HIDDEN + nb * 128 + ncol;
                    *(float2*)p0 = make_float2(cfr[mt][nt][0] + b0,
                                               cfr[mt][nt][1] + b1);
                    *(float2*)(p0 + 8 * HIDDEN) = make_float2(
                        cfr[mt][nt][2] + b0, cfr[mt][nt][3] + b1);
                }
            }
        }
    }
}

// ---------------------------------------------------------------------------
// Phase 2: scan, float2 lanes (ILP 2), HW tanh.approx for both tanhs
// (MUFU 6 -> 4 per element-step), exact sigmoid via EX2+RCP, PF=8.
// ---------------------------------------------------------------------------
#define PF 8
__global__ __launch_bounds__(128)
void brc_scan(float* __restrict__ out, const float* __restrict__ h0,
              const float* __restrict__ w_c, const float* __restrict__ w_a,
              float* __restrict__ hn) {
    const int gt = blockIdx.x * 128 + threadIdx.x;      // 0..32767
    const int e0 = gt * 2;                              // element index
    const int j = e0 & (HIDDEN - 1);
    const float2 wc = *(const float2*)(w_c + j);
    const float2 wa = *(const float2*)(w_a + j);
    float2 h = *(const float2*)(h0 + e0);
    const int STRIDE = BATCH * HIDDEN;                  // 65536 floats

    const float2* XC = (const float2*)g_xc;
    const float2* XA = (const float2*)g_xa;
    float2* OUT = (float2*)out;
    const int S2 = STRIDE / 2;                          // float2 stride

    float2 xcb[PF], xab[PF], xhb[PF];
#pragma unroll
    for (int p = 0; p < PF; p++) {
        const size_t i = (size_t)p * S2 + gt;
        xcb[p] = __ldcs(XC + i);
        xab[p] = __ldcs(XA + i);
        xhb[p] = __ldcs(OUT + i);
    }

    size_t idx = (size_t)gt;
#pragma unroll 8
    for (int t = 0; t < SEQ; ++t, idx += S2) {
        const int sl = t & (PF - 1);
        const float2 xc_c = xcb[sl], xa_c = xab[sl], xh_c = xhb[sl];
        if (t + PF < SEQ) {
            const size_t nxt = idx + (size_t)PF * S2;
            xcb[sl] = __ldcs(XC + nxt);
            xab[sl] = __ldcs(XA + nxt);
            xhb[sl] = __ldcs(OUT + nxt);
        }
        // lane x
        {
            const float c  = __fdividef(1.0f, 1.0f + __expf(-(xc_c.x + wc.x * h.x)));
            const float a  = 1.0f + tanh_ap(xa_c.x + wa.x * h.x);
            const float t3 = tanh_ap(xh_c.x + a * h.x);
            h.x = fmaf(c, h.x - t3, t3);
        }
        // lane y
        {
            const float c  = __fdividef(1.0f, 1.0f + __expf(-(xc_c.y + wc.y * h.y)));
            const float a  = 1.0f + tanh_ap(xa_c.y + wa.y * h.y);
            const float t3 = tanh_ap(xh_c.y + a * h.y);
            h.y = fmaf(c, h.y - t3, t3);
        }
        __stcs(OUT + idx, h);
    }
    if (hn) *(float2*)(hn + e0) = h;
}

// ---------------------------------------------------------------------------
extern "C" void kernel_launch(void* const* d_in, const int* in_sizes, int n_in,
                              void* d_out, int out_size) {
    const float* x  = (const float*)d_in[0];
    const float* h0 = (const float*)d_in[1];
    const float* Uc = (const float*)d_in[2];
    const float* wc = (const float*)d_in[3];
    const float* bc = (const float*)d_in[4];
    const float* Ua = (const float*)d_in[5];
    const float* wa = (const float*)d_in[6];
    const float* ba = (const float*)d_in[7];
    const float* Uh = (const float*)d_in[8];

    float* out = (float*)d_out;
    const size_t out_elems = (size_t)SEQ * BATCH * HIDDEN;
    float* hn = ((size_t)out_size >= out_elems + (size_t)BATCH * HIDDEN)
                    ? (out + out_elems) : nullptr;

    // Pre-pass: fp32 -> bf16 hi/lo splits
    splitA<<<(MDIM * INPUT / 8) / 256, 256>>>(x);
    dim3 gb(HIDDEN * INPUT / 8 / 256, 3);
    splitB3<<<gb, 256>>>(Uc, Ua, Uh);

    // Phase 1: persistent-B mma.sync GEMMs (3-stage A pipeline)
    cudaFuncSetAttribute(brc_gemm_pb,
                         cudaFuncAttributeMaxDynamicSharedMemorySize, SMEM_TOT);
    dim3 grid(12, 256);
    brc_gemm_pb<<<grid, 256, SMEM_TOT>>>(bc, ba, out);

    // Phase 2: recurrent scan, float2 lanes, in place over xh
    brc_scan<<<(BATCH * HIDDEN / 2) / 128, 128>>>(out, h0, wc, wa, hn);
}